// round 1
// baseline (speedup 1.0000x reference)
#include <cuda_runtime.h>
#include <math.h>

#define S_LEN 4096
#define DM    768
#define NH    12
#define HD    64

// Scratch (no cudaMalloc allowed): q,k,v projections + attention output, [S][768] each.
__device__ float g_q[S_LEN * DM];
__device__ float g_k[S_LEN * DM];
__device__ float g_v[S_LEN * DM];
__device__ float g_att[S_LEN * DM];

// ---------------------------------------------------------------------------
// Tiled fp32 GEMM: C[M,N] = A[M,K] @ B[K,N] (+ bias). BM=BN=64, BK=16,
// 256 threads, 4x4 micro-tile per thread, float4 shared loads.
// ---------------------------------------------------------------------------
__global__ __launch_bounds__(256) void gemm64(
    const float* __restrict__ A, const float* __restrict__ B,
    const float* __restrict__ bias, float* __restrict__ C,
    int M, int N, int K)
{
    __shared__ float As[16][68];   // As[k][i]  (A transposed in SMEM)
    __shared__ float Bs[16][68];   // Bs[k][j]

    const int tid = threadIdx.x;
    const int tx  = tid & 15;      // 0..15  -> n micro
    const int ty  = tid >> 4;      // 0..15  -> m micro
    const int m0  = blockIdx.y * 64;
    const int n0  = blockIdx.x * 64;

    const int arow = tid >> 2;           // 0..63
    const int acol = (tid & 3) * 4;      // 0,4,8,12
    const int brow = tid >> 4;           // 0..15
    const int bcol = (tid & 15) * 4;     // 0..60

    float acc[4][4];
#pragma unroll
    for (int i = 0; i < 4; i++)
#pragma unroll
        for (int j = 0; j < 4; j++) acc[i][j] = 0.f;

    for (int k0 = 0; k0 < K; k0 += 16) {
        float4 av = *(const float4*)&A[(size_t)(m0 + arow) * K + k0 + acol];
        As[acol + 0][arow] = av.x;
        As[acol + 1][arow] = av.y;
        As[acol + 2][arow] = av.z;
        As[acol + 3][arow] = av.w;
        *(float4*)&Bs[brow][bcol] =
            *(const float4*)&B[(size_t)(k0 + brow) * N + n0 + bcol];
        __syncthreads();

#pragma unroll
        for (int kk = 0; kk < 16; kk++) {
            float4 a4 = *(const float4*)&As[kk][ty * 4];
            float4 b4 = *(const float4*)&Bs[kk][tx * 4];
            float ar[4] = {a4.x, a4.y, a4.z, a4.w};
            float br[4] = {b4.x, b4.y, b4.z, b4.w};
#pragma unroll
            for (int i = 0; i < 4; i++)
#pragma unroll
                for (int j = 0; j < 4; j++)
                    acc[i][j] = fmaf(ar[i], br[j], acc[i][j]);
        }
        __syncthreads();
    }

#pragma unroll
    for (int i = 0; i < 4; i++) {
#pragma unroll
        for (int j = 0; j < 4; j++) {
            float b = bias ? bias[n0 + tx * 4 + j] : 0.f;
            C[(size_t)(m0 + ty * 4 + i) * N + n0 + tx * 4 + j] = acc[i][j] + b;
        }
    }
}

// ---------------------------------------------------------------------------
// Flash attention, fp32, causal. One block = (64 query rows) x (1 head).
// Online softmax; scores computed as 64x64 GEMM tiles with 4x4 micro-tiles;
// P staged through SMEM (transposed) for the PV GEMM.
// SMEM: Qs[64][68] (d-major), Ks[64][68] (d-major), Ps[64][68] (j-major,
// transposed), Vs[64][64] (j-major). Total 68608 B -> dynamic SMEM.
// ---------------------------------------------------------------------------
__global__ __launch_bounds__(256) void attn_kernel(
    const float* __restrict__ q, const float* __restrict__ k,
    const float* __restrict__ v, float* __restrict__ o)
{
    extern __shared__ float sm[];
    float* Qs = sm;                 // [d][i] stride 68
    float* Ks = Qs + 64 * 68;       // [d][j] stride 68
    float* Ps = Ks + 64 * 68;       // [j][i] stride 68
    float* Vs = Ps + 64 * 68;       // [j][d] stride 64

    const int h   = blockIdx.y;
    const int iq  = blockIdx.x;
    const int tid = threadIdx.x;
    const int tx  = tid & 15;
    const int ty  = tid >> 4;
    const int i0  = ty * 4;         // query-row micro offset
    const int c0  = tx * 4;         // key-col / dv micro offset

    const size_t hoff = (size_t)h * HD;

    // Load Q tile, transposed: Qs[d][i]
#pragma unroll
    for (int rep = 0; rep < 4; rep++) {
        int f  = rep * 256 + tid;     // float4 index, 0..1023
        int r  = f >> 4;              // row within tile, 0..63
        int d0 = (f & 15) * 4;        // 0..60
        float4 val = *(const float4*)&q[hoff + (size_t)(iq * 64 + r) * DM + d0];
        Qs[(d0 + 0) * 68 + r] = val.x;
        Qs[(d0 + 1) * 68 + r] = val.y;
        Qs[(d0 + 2) * 68 + r] = val.z;
        Qs[(d0 + 3) * 68 + r] = val.w;
    }

    float acc[4][4];
    float mi[4], li[4];
#pragma unroll
    for (int i = 0; i < 4; i++) {
        mi[i] = -1e30f;
        li[i] = 0.f;
#pragma unroll
        for (int j = 0; j < 4; j++) acc[i][j] = 0.f;
    }
    __syncthreads();

    for (int kt = 0; kt <= iq; kt++) {
        // Load K (transposed) and V (direct) tiles
#pragma unroll
        for (int rep = 0; rep < 4; rep++) {
            int f  = rep * 256 + tid;
            int r  = f >> 4;
            int d0 = (f & 15) * 4;
            size_t gsrc = hoff + (size_t)(kt * 64 + r) * DM + d0;
            float4 kv = *(const float4*)&k[gsrc];
            Ks[(d0 + 0) * 68 + r] = kv.x;
            Ks[(d0 + 1) * 68 + r] = kv.y;
            Ks[(d0 + 2) * 68 + r] = kv.z;
            Ks[(d0 + 3) * 68 + r] = kv.w;
            *(float4*)&Vs[r * 64 + d0] = *(const float4*)&v[gsrc];
        }
        __syncthreads();

        // S = (Q @ K^T) / 8
        float s[4][4];
#pragma unroll
        for (int i = 0; i < 4; i++)
#pragma unroll
            for (int j = 0; j < 4; j++) s[i][j] = 0.f;

#pragma unroll 8
        for (int d = 0; d < 64; d++) {
            float4 a4 = *(const float4*)&Qs[d * 68 + i0];
            float4 b4 = *(const float4*)&Ks[d * 68 + c0];
            float ar[4] = {a4.x, a4.y, a4.z, a4.w};
            float br[4] = {b4.x, b4.y, b4.z, b4.w};
#pragma unroll
            for (int i = 0; i < 4; i++)
#pragma unroll
                for (int j = 0; j < 4; j++)
                    s[i][j] = fmaf(ar[i], br[j], s[i][j]);
        }

        const bool diag = (kt == iq);
#pragma unroll
        for (int i = 0; i < 4; i++) {
#pragma unroll
            for (int j = 0; j < 4; j++) {
                s[i][j] *= 0.125f;   // 1/sqrt(64)
                if (diag && (c0 + j) > (i0 + i)) s[i][j] = -1e30f;
            }
        }

        // Online softmax per row (row spread over 16 tx lanes)
#pragma unroll
        for (int i = 0; i < 4; i++) {
            float rmax = fmaxf(fmaxf(s[i][0], s[i][1]), fmaxf(s[i][2], s[i][3]));
#pragma unroll
            for (int off = 8; off > 0; off >>= 1)
                rmax = fmaxf(rmax, __shfl_xor_sync(0xFFFFFFFFu, rmax, off));
            float newm  = fmaxf(mi[i], rmax);
            float alpha = __expf(mi[i] - newm);
            float rsum  = 0.f;
#pragma unroll
            for (int j = 0; j < 4; j++) {
                s[i][j] = __expf(s[i][j] - newm);
                rsum += s[i][j];
            }
#pragma unroll
            for (int off = 8; off > 0; off >>= 1)
                rsum += __shfl_xor_sync(0xFFFFFFFFu, rsum, off);
            li[i] = li[i] * alpha + rsum;
            mi[i] = newm;
#pragma unroll
            for (int j = 0; j < 4; j++) acc[i][j] *= alpha;
        }

        // Stage P transposed: Ps[j][i]
#pragma unroll
        for (int j = 0; j < 4; j++) {
            float4 pv = make_float4(s[0][j], s[1][j], s[2][j], s[3][j]);
            *(float4*)&Ps[(c0 + j) * 68 + i0] = pv;
        }
        __syncthreads();

        // O += P @ V
#pragma unroll 8
        for (int j = 0; j < 64; j++) {
            float4 a4 = *(const float4*)&Ps[j * 68 + i0];
            float4 b4 = *(const float4*)&Vs[j * 64 + c0];
            float ar[4] = {a4.x, a4.y, a4.z, a4.w};
            float br[4] = {b4.x, b4.y, b4.z, b4.w};
#pragma unroll
            for (int i = 0; i < 4; i++)
#pragma unroll
                for (int jj = 0; jj < 4; jj++)
                    acc[i][jj] = fmaf(ar[i], br[jj], acc[i][jj]);
        }
        __syncthreads();
    }

    // Epilogue: normalize and write [S][H*DV] layout
#pragma unroll
    for (int i = 0; i < 4; i++) {
        float inv = 1.0f / li[i];
#pragma unroll
        for (int j = 0; j < 4; j++)
            o[hoff + (size_t)(iq * 64 + i0 + i) * DM + c0 + j] = acc[i][j] * inv;
    }
}

// ---------------------------------------------------------------------------
// Launch
// ---------------------------------------------------------------------------
static const int ATTN_SMEM = (64 * 68 * 3 + 64 * 64) * 4;  // 68608 B

extern "C" void kernel_launch(void* const* d_in, const int* in_sizes, int n_in,
                              void* d_out, int out_size)
{
    const float* Q  = (const float*)d_in[0];
    const float* K  = (const float*)d_in[1];
    const float* V  = (const float*)d_in[2];
    const float* Wq = (const float*)d_in[3];
    const float* Wk = (const float*)d_in[4];
    const float* Wv = (const float*)d_in[5];
    const float* Wo = (const float*)d_in[6];
    const float* bo = (const float*)d_in[7];
    float* out = (float*)d_out;

    float *gq, *gk, *gv, *ga;
    cudaGetSymbolAddress((void**)&gq, g_q);
    cudaGetSymbolAddress((void**)&gk, g_k);
    cudaGetSymbolAddress((void**)&gv, g_v);
    cudaGetSymbolAddress((void**)&ga, g_att);

    static bool attr_set = false;
    if (!attr_set) {
        cudaFuncSetAttribute(attn_kernel,
                             cudaFuncAttributeMaxDynamicSharedMemorySize,
                             ATTN_SMEM);
        attr_set = true;
    }

    dim3 gproj(DM / 64, S_LEN / 64);   // (12, 64)
    gemm64<<<gproj, 256>>>(Q, Wq, nullptr, gq, S_LEN, DM, DM);
    gemm64<<<gproj, 256>>>(K, Wk, nullptr, gk, S_LEN, DM, DM);
    gemm64<<<gproj, 256>>>(V, Wv, nullptr, gv, S_LEN, DM, DM);

    dim3 gattn(S_LEN / 64, NH);        // (64, 12)
    attn_kernel<<<gattn, 256, ATTN_SMEM>>>(gq, gk, gv, ga);

    gemm64<<<gproj, 256>>>(ga, Wo, bo, out, S_LEN, DM, DM);
}

// round 3
// speedup vs baseline: 3.1193x; 3.1193x over previous
#include <cuda_runtime.h>
#include <stdint.h>

#define S_LEN 4096
#define DM    768
#define NH    12
#define HD    64

// Scratch (no cudaMalloc allowed)
__device__ float g_q[S_LEN * DM];
__device__ float g_k[S_LEN * DM];
__device__ float g_v[S_LEN * DM];
__device__ float g_att[S_LEN * DM];

__device__ __forceinline__ uint32_t f2tf(float x) {
    uint32_t r;
    asm("cvt.rna.tf32.f32 %0, %1;" : "=r"(r) : "f"(x));
    return r;
}

__device__ __forceinline__ void mma_tf32(float c[4],
    uint32_t a0, uint32_t a1, uint32_t a2, uint32_t a3,
    uint32_t b0, uint32_t b1)
{
    asm volatile(
        "mma.sync.aligned.m16n8k8.row.col.f32.tf32.tf32.f32 "
        "{%0,%1,%2,%3}, {%4,%5,%6,%7}, {%8,%9}, {%0,%1,%2,%3};"
        : "+f"(c[0]), "+f"(c[1]), "+f"(c[2]), "+f"(c[3])
        : "r"(a0), "r"(a1), "r"(a2), "r"(a3), "r"(b0), "r"(b1));
}

// ---------------------------------------------------------------------------
// GEMM: C[M,N] = A[M,K] @ B[K,N] (+bias). Block 128x64, Ktile 32, 256 thr.
// 8 warps = 4(m) x 2(n); warp tile 32x32 = 2 m-tiles x 4 n-tiles of m16n8k8.
// ---------------------------------------------------------------------------
#define AST 36
#define BST 72

__global__ __launch_bounds__(256) void gemm_mma(
    const float* __restrict__ A, const float* __restrict__ B,
    const float* __restrict__ bias, float* __restrict__ C,
    int M, int N, int K)
{
    __shared__ uint32_t As[128 * AST];
    __shared__ uint32_t Bs[32 * BST];

    const int tid  = threadIdx.x;
    const int warp = tid >> 5, lane = tid & 31;
    const int g = lane >> 2, tg = lane & 3;
    const int wm = warp >> 1, wn = warp & 1;
    const int m0 = blockIdx.y * 128, n0 = blockIdx.x * 64;
    const int mb = wm * 32, nbw = wn * 32;

    float acc[2][4][4];
#pragma unroll
    for (int mt = 0; mt < 2; mt++)
#pragma unroll
        for (int nt = 0; nt < 4; nt++)
#pragma unroll
            for (int c = 0; c < 4; c++) acc[mt][nt][c] = 0.f;

    for (int k0 = 0; k0 < K; k0 += 32) {
        // A tile 128x32 (1024 float4)
#pragma unroll
        for (int it = 0; it < 4; it++) {
            int idx = it * 256 + tid;
            int r = idx >> 3, c4 = (idx & 7) * 4;
            float4 v = *(const float4*)&A[(size_t)(m0 + r) * K + k0 + c4];
            uint4 u = make_uint4(f2tf(v.x), f2tf(v.y), f2tf(v.z), f2tf(v.w));
            *(uint4*)&As[r * AST + c4] = u;
        }
        // B tile 32x64 (512 float4)
#pragma unroll
        for (int it = 0; it < 2; it++) {
            int idx = it * 256 + tid;
            int r = idx >> 4, c4 = (idx & 15) * 4;
            float4 v = *(const float4*)&B[(size_t)(k0 + r) * N + n0 + c4];
            uint4 u = make_uint4(f2tf(v.x), f2tf(v.y), f2tf(v.z), f2tf(v.w));
            *(uint4*)&Bs[r * BST + c4] = u;
        }
        __syncthreads();

#pragma unroll
        for (int kk = 0; kk < 4; kk++) {
            uint32_t a[2][4], b[4][2];
#pragma unroll
            for (int mt = 0; mt < 2; mt++) {
                int r = mb + mt * 16 + g;
                int kc = kk * 8 + tg;
                a[mt][0] = As[r * AST + kc];
                a[mt][1] = As[(r + 8) * AST + kc];
                a[mt][2] = As[r * AST + kc + 4];
                a[mt][3] = As[(r + 8) * AST + kc + 4];
            }
#pragma unroll
            for (int nt = 0; nt < 4; nt++) {
                int c = nbw + nt * 8 + g;
                b[nt][0] = Bs[(kk * 8 + tg) * BST + c];
                b[nt][1] = Bs[(kk * 8 + tg + 4) * BST + c];
            }
#pragma unroll
            for (int mt = 0; mt < 2; mt++)
#pragma unroll
                for (int nt = 0; nt < 4; nt++)
                    mma_tf32(acc[mt][nt], a[mt][0], a[mt][1], a[mt][2], a[mt][3],
                             b[nt][0], b[nt][1]);
        }
        __syncthreads();
    }

#pragma unroll
    for (int mt = 0; mt < 2; mt++) {
#pragma unroll
        for (int nt = 0; nt < 4; nt++) {
            int r = m0 + mb + mt * 16 + g;
            int c = n0 + nbw + nt * 8 + 2 * tg;
            float b0 = 0.f, b1 = 0.f;
            if (bias) { b0 = bias[c]; b1 = bias[c + 1]; }
            float2 lo = make_float2(acc[mt][nt][0] + b0, acc[mt][nt][1] + b1);
            float2 hi = make_float2(acc[mt][nt][2] + b0, acc[mt][nt][3] + b1);
            *(float2*)&C[(size_t)r * N + c] = lo;
            *(float2*)&C[(size_t)(r + 8) * N + c] = hi;
        }
    }
}

// ---------------------------------------------------------------------------
// Flash attention, tf32 mma, causal. Block = 128 q-rows x 1 head, 256 thr.
// Warp w owns rows w*16..w*16+15.
// ---------------------------------------------------------------------------
#define QST 68
#define KST 68
#define VST 72
#define PST 68
#define ATTN_SMEM ((128*QST + 64*KST + 64*VST + 128*PST) * 4)  // 105472 B

__global__ __launch_bounds__(256, 2) void attn_mma(
    const float* __restrict__ q, const float* __restrict__ k,
    const float* __restrict__ v, float* __restrict__ o)
{
    extern __shared__ uint32_t sm[];
    uint32_t* Qs = sm;                  // [q][d]   128 x QST
    uint32_t* Ks = Qs + 128 * QST;      // [key][d]  64 x KST
    uint32_t* Vs = Ks + 64 * KST;       // [key][dv] 64 x VST
    uint32_t* Ps = Vs + 64 * VST;       // [q][key] 128 x PST

    const int h = blockIdx.y;
    const int t = blockIdx.x;
    const int iq = (t & 1) ? (31 - (t >> 1)) : (t >> 1);  // heavy/light interleave
    const int tid = threadIdx.x, warp = tid >> 5, lane = tid & 31;
    const int g = lane >> 2, tg = lane & 3;
    const size_t hoff = (size_t)h * HD;
    const int qrow = iq * 128 + warp * 16 + g;   // this thread: rows qrow, qrow+8
    const int wrow = warp * 16 + g;

    // Load Q tile (128 x 64 = 2048 float4) into SMEM as tf32
#pragma unroll
    for (int it = 0; it < 8; it++) {
        int idx = it * 256 + tid;
        int r = idx >> 4, d4 = (idx & 15) * 4;
        float4 val = *(const float4*)&q[(size_t)(iq * 128 + r) * DM + hoff + d4];
        uint4 u = make_uint4(f2tf(val.x), f2tf(val.y), f2tf(val.z), f2tf(val.w));
        *(uint4*)&Qs[r * QST + d4] = u;
    }

    float of[8][4];
#pragma unroll
    for (int nt = 0; nt < 8; nt++)
#pragma unroll
        for (int c = 0; c < 4; c++) of[nt][c] = 0.f;
    float m0r = -1e30f, m1r = -1e30f, l0 = 0.f, l1 = 0.f;

    __syncthreads();

    const int ktmax = 2 * iq + 1;
    for (int kt = 0; kt <= ktmax; kt++) {
        // Load K, V tiles (each 64 keys x 64 d = 1024 float4)
#pragma unroll
        for (int it = 0; it < 4; it++) {
            int idx = it * 256 + tid;
            int key = idx >> 4, d4 = (idx & 15) * 4;
            size_t gidx = hoff + (size_t)(kt * 64 + key) * DM + d4;
            float4 kv = *(const float4*)&k[gidx];
            *(uint4*)&Ks[key * KST + d4] =
                make_uint4(f2tf(kv.x), f2tf(kv.y), f2tf(kv.z), f2tf(kv.w));
            float4 vv = *(const float4*)&v[gidx];
            *(uint4*)&Vs[key * VST + d4] =
                make_uint4(f2tf(vv.x), f2tf(vv.y), f2tf(vv.z), f2tf(vv.w));
        }
        __syncthreads();

        // S = Q @ K^T   (warp: 16 rows x 64 keys = 8 n-tiles)
        float s[8][4];
#pragma unroll
        for (int nt = 0; nt < 8; nt++)
#pragma unroll
            for (int c = 0; c < 4; c++) s[nt][c] = 0.f;

#pragma unroll
        for (int ks = 0; ks < 8; ks++) {
            int kc = ks * 8 + tg;
            uint32_t a0 = Qs[wrow * QST + kc];
            uint32_t a1 = Qs[(wrow + 8) * QST + kc];
            uint32_t a2 = Qs[wrow * QST + kc + 4];
            uint32_t a3 = Qs[(wrow + 8) * QST + kc + 4];
#pragma unroll
            for (int nt = 0; nt < 8; nt++) {
                uint32_t b0 = Ks[(nt * 8 + g) * KST + kc];
                uint32_t b1 = Ks[(nt * 8 + g) * KST + kc + 4];
                mma_tf32(s[nt], a0, a1, a2, a3, b0, b1);
            }
        }

        // scale + causal mask
        const bool need_mask = (kt >= 2 * iq);
#pragma unroll
        for (int nt = 0; nt < 8; nt++) {
            s[nt][0] *= 0.125f; s[nt][1] *= 0.125f;
            s[nt][2] *= 0.125f; s[nt][3] *= 0.125f;
            if (need_mask) {
                int col = kt * 64 + nt * 8 + 2 * tg;
                if (col     > qrow)     s[nt][0] = -1e30f;
                if (col + 1 > qrow)     s[nt][1] = -1e30f;
                if (col     > qrow + 8) s[nt][2] = -1e30f;
                if (col + 1 > qrow + 8) s[nt][3] = -1e30f;
            }
        }

        // online softmax (rows qrow, qrow+8; each row spread over 4 tg-lanes)
        float rm0 = -1e30f, rm1 = -1e30f;
#pragma unroll
        for (int nt = 0; nt < 8; nt++) {
            rm0 = fmaxf(rm0, fmaxf(s[nt][0], s[nt][1]));
            rm1 = fmaxf(rm1, fmaxf(s[nt][2], s[nt][3]));
        }
#pragma unroll
        for (int off = 1; off <= 2; off <<= 1) {
            rm0 = fmaxf(rm0, __shfl_xor_sync(0xFFFFFFFFu, rm0, off));
            rm1 = fmaxf(rm1, __shfl_xor_sync(0xFFFFFFFFu, rm1, off));
        }
        float nm0 = fmaxf(m0r, rm0), nm1 = fmaxf(m1r, rm1);
        float al0 = __expf(m0r - nm0), al1 = __expf(m1r - nm1);
        float sum0 = 0.f, sum1 = 0.f;
#pragma unroll
        for (int nt = 0; nt < 8; nt++) {
            s[nt][0] = __expf(s[nt][0] - nm0); sum0 += s[nt][0];
            s[nt][1] = __expf(s[nt][1] - nm0); sum0 += s[nt][1];
            s[nt][2] = __expf(s[nt][2] - nm1); sum1 += s[nt][2];
            s[nt][3] = __expf(s[nt][3] - nm1); sum1 += s[nt][3];
        }
#pragma unroll
        for (int off = 1; off <= 2; off <<= 1) {
            sum0 += __shfl_xor_sync(0xFFFFFFFFu, sum0, off);
            sum1 += __shfl_xor_sync(0xFFFFFFFFu, sum1, off);
        }
        l0 = l0 * al0 + sum0;  l1 = l1 * al1 + sum1;
        m0r = nm0;  m1r = nm1;
#pragma unroll
        for (int nt = 0; nt < 8; nt++) {
            of[nt][0] *= al0; of[nt][1] *= al0;
            of[nt][2] *= al1; of[nt][3] *= al1;
        }

        // stage P (warp-private rows) as tf32
#pragma unroll
        for (int nt = 0; nt < 8; nt++) {
            int pc = nt * 8 + 2 * tg;
            Ps[wrow * PST + pc]           = f2tf(s[nt][0]);
            Ps[wrow * PST + pc + 1]       = f2tf(s[nt][1]);
            Ps[(wrow + 8) * PST + pc]     = f2tf(s[nt][2]);
            Ps[(wrow + 8) * PST + pc + 1] = f2tf(s[nt][3]);
        }
        __syncwarp();

        // O += P @ V
#pragma unroll
        for (int ks = 0; ks < 8; ks++) {
            int kc = ks * 8 + tg;
            uint32_t a0 = Ps[wrow * PST + kc];
            uint32_t a1 = Ps[(wrow + 8) * PST + kc];
            uint32_t a2 = Ps[wrow * PST + kc + 4];
            uint32_t a3 = Ps[(wrow + 8) * PST + kc + 4];
#pragma unroll
            for (int nt = 0; nt < 8; nt++) {
                uint32_t b0 = Vs[kc * VST + nt * 8 + g];
                uint32_t b1 = Vs[(kc + 4) * VST + nt * 8 + g];
                mma_tf32(of[nt], a0, a1, a2, a3, b0, b1);
            }
        }
        __syncthreads();   // protect Ks/Vs before next tile load
    }

    // epilogue
    float inv0 = 1.f / l0, inv1 = 1.f / l1;
#pragma unroll
    for (int nt = 0; nt < 8; nt++) {
        size_t c = hoff + nt * 8 + 2 * tg;
        *(float2*)&o[(size_t)qrow * DM + c] =
            make_float2(of[nt][0] * inv0, of[nt][1] * inv0);
        *(float2*)&o[(size_t)(qrow + 8) * DM + c] =
            make_float2(of[nt][2] * inv1, of[nt][3] * inv1);
    }
}

// ---------------------------------------------------------------------------
// Launch
// ---------------------------------------------------------------------------
extern "C" void kernel_launch(void* const* d_in, const int* in_sizes, int n_in,
                              void* d_out, int out_size)
{
    const float* Q  = (const float*)d_in[0];
    const float* K  = (const float*)d_in[1];
    const float* V  = (const float*)d_in[2];
    const float* Wq = (const float*)d_in[3];
    const float* Wk = (const float*)d_in[4];
    const float* Wv = (const float*)d_in[5];
    const float* Wo = (const float*)d_in[6];
    const float* bo = (const float*)d_in[7];
    float* out = (float*)d_out;

    float *gq, *gk, *gv, *ga;
    cudaGetSymbolAddress((void**)&gq, g_q);
    cudaGetSymbolAddress((void**)&gk, g_k);
    cudaGetSymbolAddress((void**)&gv, g_v);
    cudaGetSymbolAddress((void**)&ga, g_att);

    static bool attr_set = false;
    if (!attr_set) {
        cudaFuncSetAttribute(attn_mma,
                             cudaFuncAttributeMaxDynamicSharedMemorySize,
                             ATTN_SMEM);
        attr_set = true;
    }

    dim3 gproj(DM / 64, S_LEN / 128);   // (12, 32)
    gemm_mma<<<gproj, 256>>>(Q, Wq, nullptr, gq, S_LEN, DM, DM);
    gemm_mma<<<gproj, 256>>>(K, Wk, nullptr, gk, S_LEN, DM, DM);
    gemm_mma<<<gproj, 256>>>(V, Wv, nullptr, gv, S_LEN, DM, DM);

    dim3 gattn(S_LEN / 128, NH);        // (32, 12)
    attn_mma<<<gattn, 256, ATTN_SMEM>>>(gq, gk, gv, ga);

    gemm_mma<<<gproj, 256>>>(ga, Wo, bo, out, S_LEN, DM, DM);
}